// round 6
// baseline (speedup 1.0000x reference)
#include <cuda_runtime.h>
#include <math.h>

#define KSZ 7
#define PAD 3

#define B_  8
#define T_  16
#define C_  256
#define HW_ 784
#define HW4_ 196          // HW_/4 (float4)
#define NBC (B_ * C_)     // 2048
#define PSROW (T_ + 2 * PAD + 1)   // 23

// Scratch (no allocations allowed)
__device__ float d_pooled[B_ * C_ * T_];      // [b][c][t]
__device__ float d_Kern[B_ * C_ * KSZ];       // [b][c][k]
__device__ float d_Yt[B_ * T_ * 64];          // [b][t][o]

// ---------------------------------------------------------------------------
// Kernel 1: spatial mean pool. One warp per (b,t,c) row (784 contiguous f32).
// Normal (caching) loads on purpose: populate L2 with x for the main kernel
// and for the next graph replay.
// ---------------------------------------------------------------------------
__global__ void pool_kernel(const float* __restrict__ x) {
    const int warp = threadIdx.x >> 5;
    const int lane = threadIdx.x & 31;
    const int row  = blockIdx.x * 8 + warp;       // (b*T + t)*C + c
    const float4* xr = reinterpret_cast<const float4*>(x) + (size_t)row * HW4_;

    float s = 0.f;
    #pragma unroll 7
    for (int i = lane; i < HW4_; i += 32) {
        float4 v = xr[i];
        s += (v.x + v.y) + (v.z + v.w);
    }
    #pragma unroll
    for (int o = 16; o > 0; o >>= 1) s += __shfl_xor_sync(0xffffffffu, s, o);

    if (lane == 0) {
        int c  = row & (C_ - 1);
        int bt = row >> 8;
        int t  = bt & (T_ - 1);
        int b  = bt >> 4;
        d_pooled[(b * C_ + c) * T_ + t] = s * (1.0f / (float)HW_);
    }
}

// ---------------------------------------------------------------------------
// Kernel 2: fused coefficients. Grid = (65, 8), 128 threads.
//   blockIdx.x < 64 : conv1d output channel o for batch b  -> d_Yt[b][t][o]
//   blockIdx.x == 64: G branch for batch b (2 channels per thread) -> d_Kern
// ---------------------------------------------------------------------------
__global__ void coeff_kernel(const float* __restrict__ Wl1,   // [64][256][7]
                             const float* __restrict__ W1,    // [32][16]
                             const float* __restrict__ W2)    // [7][32]
{
    __shared__ float ps[C_ * PSROW];
    __shared__ float red[4][T_];
    __shared__ float w1s[32 * 16];
    __shared__ float w2s[7 * 32];

    const int b   = blockIdx.y;
    const int tid = threadIdx.x;          // 0..127

    if (blockIdx.x == 64) {
        // ---- G branch ----
        for (int i = tid; i < 512; i += 128) w1s[i] = W1[i];
        for (int i = tid; i < 224; i += 128) w2s[i] = W2[i];
        __syncthreads();

        #pragma unroll
        for (int cc = 0; cc < 2; cc++) {
            const int c = tid + cc * 128;
            float p[T_];
            const float4* pp = reinterpret_cast<const float4*>(d_pooled + (b * C_ + c) * T_);
            #pragma unroll
            for (int q = 0; q < 4; q++) {
                float4 v = pp[q];
                p[q*4+0]=v.x; p[q*4+1]=v.y; p[q*4+2]=v.z; p[q*4+3]=v.w;
            }
            float s[KSZ];
            #pragma unroll
            for (int k = 0; k < KSZ; k++) s[k] = 0.f;
            for (int u = 0; u < 32; u++) {
                float acc = 0.f;
                #pragma unroll
                for (int t = 0; t < T_; t++) acc += p[t] * w1s[u * 16 + t];
                float g = tanhf(acc);
                #pragma unroll
                for (int k = 0; k < KSZ; k++) s[k] += g * w2s[k * 32 + u];
            }
            float m = s[0];
            #pragma unroll
            for (int k = 1; k < KSZ; k++) m = fmaxf(m, s[k]);
            float e[KSZ], sum = 0.f;
            #pragma unroll
            for (int k = 0; k < KSZ; k++) { e[k] = expf(s[k] - m); sum += e[k]; }
            float inv = 1.0f / sum;
            #pragma unroll
            for (int k = 0; k < KSZ; k++)
                d_Kern[(b * C_ + c) * KSZ + k] = e[k] * inv;
        }
        return;
    }

    // ---- L-branch conv1d: output channel o = blockIdx.x ----
    const int o = blockIdx.x;
    const int lane = tid & 31;
    const int wrp  = tid >> 5;

    for (int i = tid; i < C_ * PSROW; i += 128) ps[i] = 0.f;
    __syncthreads();
    const float4* pp = reinterpret_cast<const float4*>(d_pooled + b * C_ * T_);
    for (int i = tid; i < C_ * T_ / 4; i += 128) {
        float4 v = pp[i];
        int e0 = i * 4;
        int c = e0 >> 4, t = e0 & 15;
        float* r = &ps[c * PSROW + PAD + t];
        r[0] = v.x; r[1] = v.y; r[2] = v.z; r[3] = v.w;
    }
    __syncthreads();

    float acc[T_];
    #pragma unroll
    for (int t = 0; t < T_; t++) acc[t] = 0.f;

    const float* w = Wl1 + o * (C_ * KSZ);
    #pragma unroll
    for (int ii = 0; ii < 2; ii++) {
        const int i = tid * 2 + ii;
        float wk[KSZ];
        #pragma unroll
        for (int k = 0; k < KSZ; k++) wk[k] = w[i * KSZ + k];
        float pv[T_ + 2 * PAD];
        #pragma unroll
        for (int j = 0; j < T_ + 2 * PAD; j++) pv[j] = ps[i * PSROW + j];
        #pragma unroll
        for (int t = 0; t < T_; t++) {
            #pragma unroll
            for (int k = 0; k < KSZ; k++)
                acc[t] += wk[k] * pv[t + k];
        }
    }

    #pragma unroll
    for (int off = 16; off > 0; off >>= 1) {
        #pragma unroll
        for (int t = 0; t < T_; t++)
            acc[t] += __shfl_xor_sync(0xffffffffu, acc[t], off);
    }
    if (lane == 0) {
        #pragma unroll
        for (int t = 0; t < T_; t++) red[wrp][t] = acc[t];
    }
    __syncthreads();
    if (tid < T_) {
        float s = red[0][tid] + red[1][tid] + red[2][tid] + red[3][tid];
        d_Yt[(b * T_ + tid) * 64 + o] = tanhf(s);   // transposed store
    }
}

// ---------------------------------------------------------------------------
// Kernel 3: main. One block per (b,c), 196 threads (one float4 lane each).
//   All 16 x-slice loads issued up front (MLP=16); gates computed concurrently
//   by threads 0..15; sync; scale + 7-tap conv; EVICT-FIRST streaming stores
//   (__stcs) so the 103MB of out writes do not evict x from L2 — x stays
//   L2-resident across graph replays.
// ---------------------------------------------------------------------------
__global__ void __launch_bounds__(196)
tam_main_kernel(const float* __restrict__ x, float* __restrict__ out,
                const float* __restrict__ Wl2)   // [256][64]
{
    __shared__ float lrs[T_];
    const int bc  = blockIdx.x;
    const int b   = bc >> 8;
    const int c   = bc & (C_ - 1);
    const int tid = threadIdx.x;     // 0..195

    const size_t base = (size_t)(b * T_ * C_ + c) * HW4_ + tid;   // t=0 slice
    const int tstride = C_ * HW4_;
    const float4* xp = reinterpret_cast<const float4*>(x) + base;
    float4*       op = reinterpret_cast<float4*>(out) + base;

    // front-batched, ungated x loads — independent of gate math below
    float4 g[T_];
    #pragma unroll
    for (int t = 0; t < T_; t++) g[t] = xp[t * tstride];

    // gates (threads 0..15), overlapped with the x-load latency
    if (tid < T_) {
        const float4* wv = reinterpret_cast<const float4*>(Wl2 + c * 64);
        const float4* yv = reinterpret_cast<const float4*>(d_Yt + (b * T_ + tid) * 64);
        float acc = 0.f;
        #pragma unroll
        for (int q = 0; q < 16; q++) {
            float4 wq = wv[q], yq = yv[q];
            acc += wq.x * yq.x + wq.y * yq.y + wq.z * yq.z + wq.w * yq.w;
        }
        lrs[tid] = 1.0f / (1.0f + expf(-acc));
    }

    float kr[KSZ];
    #pragma unroll
    for (int k = 0; k < KSZ; k++) kr[k] = d_Kern[bc * KSZ + k];

    __syncthreads();

    #pragma unroll
    for (int t = 0; t < T_; t++) {
        float l = lrs[t];
        g[t].x *= l; g[t].y *= l; g[t].z *= l; g[t].w *= l;
    }

    #pragma unroll
    for (int t = 0; t < T_; t++) {
        float4 a; a.x = a.y = a.z = a.w = 0.f;
        #pragma unroll
        for (int k = 0; k < KSZ; k++) {
            int u = t + k - PAD;
            if (u >= 0 && u < T_) {          // constant-folded
                float kk = kr[k];
                a.x += kk * g[u].x;
                a.y += kk * g[u].y;
                a.z += kk * g[u].z;
                a.w += kk * g[u].w;
            }
        }
        __stcs(op + t * tstride, a);          // evict-first: protect x in L2
    }
}

// ---------------------------------------------------------------------------
extern "C" void kernel_launch(void* const* d_in, const int* in_sizes, int n_in,
                              void* d_out, int out_size) {
    const float* x   = (const float*)d_in[0];
    const float* W1  = (const float*)d_in[1];
    const float* W2  = (const float*)d_in[2];
    const float* Wl1 = (const float*)d_in[3];
    const float* Wl2 = (const float*)d_in[4];
    float* out = (float*)d_out;

    pool_kernel<<<(B_ * T_ * C_) / 8, 256>>>(x);
    coeff_kernel<<<dim3(65, B_), 128>>>(Wl1, W1, W2);
    tam_main_kernel<<<NBC, 196>>>(x, out, Wl2);
}

// round 7
// speedup vs baseline: 1.0485x; 1.0485x over previous
#include <cuda_runtime.h>
#include <math.h>
#include <stdint.h>

#define KSZ 7
#define PAD 3

#define B_  8
#define T_  16
#define C_  256
#define HW_ 784
#define HW4_ 196                  // HW_/4 (float4 per slice)
#define SLICE_BYTES 3136          // HW_ * 4
#define NBC (B_ * C_)             // 2048
#define PSROW (T_ + 2 * PAD + 1)  // 23

#define NSLOT 19                  // 16 in-slices + 3 spill slots for out[0..2]
#define MAIN_SMEM (NSLOT * SLICE_BYTES + 16)   // + mbarrier
#define POOL_ROWS 16
#define POOL_BYTES (POOL_ROWS * SLICE_BYTES)   // 50176
#define POOL_SMEM (POOL_BYTES + 16)

// Scratch (no allocations allowed)
__device__ float d_pooled[B_ * C_ * T_];      // [b][c][t]
__device__ float d_Kern[B_ * C_ * KSZ];       // [b][c][k]
__device__ float d_Yt[B_ * T_ * 64];          // [b][t][o]

// ---------------- PTX helpers ----------------
__device__ __forceinline__ uint32_t smem_u32(const void* p) {
    return (uint32_t)__cvta_generic_to_shared(p);
}
#define MBAR_INIT(a, n) \
    asm volatile("mbarrier.init.shared.b64 [%0], %1;" :: "r"(a), "r"(n) : "memory")
#define MBAR_EXPECT(a, bytes) \
    asm volatile("mbarrier.arrive.expect_tx.shared.b64 _, [%0], %1;" :: "r"(a), "r"(bytes) : "memory")
#define MBAR_WAIT(a, ph) do {                                                   \
    uint32_t _done = 0;                                                         \
    while (!_done) {                                                            \
        asm volatile("{\n\t.reg .pred p;\n\t"                                   \
            "mbarrier.try_wait.parity.acquire.cta.shared::cta.b64 p, [%1], %2, 0x989680;\n\t" \
            "selp.b32 %0, 1, 0, p;\n\t}"                                        \
            : "=r"(_done) : "r"(a), "r"(ph) : "memory");                        \
    }                                                                           \
} while (0)
#define BULK_G2S(dst_s, src_g, bytes, mbar) \
    asm volatile("cp.async.bulk.shared::cluster.global.mbarrier::complete_tx::bytes [%0], [%1], %2, [%3];" \
        :: "r"(dst_s), "l"(src_g), "r"(bytes), "r"(mbar) : "memory")
#define BULK_S2G(dst_g, src_s, bytes) \
    asm volatile("cp.async.bulk.global.shared::cta.bulk_group [%0], [%1], %2;" \
        :: "l"(dst_g), "r"(src_s), "r"(bytes) : "memory")
#define BULK_COMMIT() asm volatile("cp.async.bulk.commit_group;" ::: "memory")
#define BULK_WAIT0()  asm volatile("cp.async.bulk.wait_group 0;" ::: "memory")
#define FENCE_ASYNC() asm volatile("fence.proxy.async;" ::: "memory")

// ---------------------------------------------------------------------------
// Kernel 1: spatial mean pool via TMA. Block = 16 contiguous rows (50 KB),
// 512 threads; one bulk load, then warp-per-row LDS reduction.
// ---------------------------------------------------------------------------
__global__ void __launch_bounds__(512)
pool_kernel(const float* __restrict__ x) {
    extern __shared__ __align__(128) char smem[];
    float4* sm4 = reinterpret_cast<float4*>(smem);
    const uint32_t mbar = smem_u32(smem + POOL_BYTES);

    const int tid  = threadIdx.x;
    const int warp = tid >> 5;
    const int lane = tid & 31;
    const int row0 = blockIdx.x * POOL_ROWS;

    if (tid == 0) MBAR_INIT(mbar, 1);
    __syncthreads();
    if (tid == 0) {
        MBAR_EXPECT(mbar, (uint32_t)POOL_BYTES);
        BULK_G2S(smem_u32(smem), x + (size_t)row0 * HW_, (uint32_t)POOL_BYTES, mbar);
    }
    MBAR_WAIT(mbar, 0);

    // warp w reduces row w (196 float4 in smem)
    const float4* r = sm4 + warp * HW4_;
    float s = 0.f;
    #pragma unroll 7
    for (int i = lane; i < HW4_; i += 32) {
        float4 v = r[i];
        s += (v.x + v.y) + (v.z + v.w);
    }
    #pragma unroll
    for (int o = 16; o > 0; o >>= 1) s += __shfl_xor_sync(0xffffffffu, s, o);

    if (lane == 0) {
        int row = row0 + warp;          // (b*T + t)*C + c
        int c  = row & (C_ - 1);
        int bt = row >> 8;
        int t  = bt & (T_ - 1);
        int b  = bt >> 4;
        d_pooled[(b * C_ + c) * T_ + t] = s * (1.0f / (float)HW_);
    }
}

// ---------------------------------------------------------------------------
// Kernel 2: fused coefficients (unchanged). Grid = (65, 8), 128 threads.
// ---------------------------------------------------------------------------
__global__ void coeff_kernel(const float* __restrict__ Wl1,   // [64][256][7]
                             const float* __restrict__ W1,    // [32][16]
                             const float* __restrict__ W2)    // [7][32]
{
    __shared__ float ps[C_ * PSROW];
    __shared__ float red[4][T_];
    __shared__ float w1s[32 * 16];
    __shared__ float w2s[7 * 32];

    const int b   = blockIdx.y;
    const int tid = threadIdx.x;

    if (blockIdx.x == 64) {
        for (int i = tid; i < 512; i += 128) w1s[i] = W1[i];
        for (int i = tid; i < 224; i += 128) w2s[i] = W2[i];
        __syncthreads();

        #pragma unroll
        for (int cc = 0; cc < 2; cc++) {
            const int c = tid + cc * 128;
            float p[T_];
            const float4* pp = reinterpret_cast<const float4*>(d_pooled + (b * C_ + c) * T_);
            #pragma unroll
            for (int q = 0; q < 4; q++) {
                float4 v = pp[q];
                p[q*4+0]=v.x; p[q*4+1]=v.y; p[q*4+2]=v.z; p[q*4+3]=v.w;
            }
            float s[KSZ];
            #pragma unroll
            for (int k = 0; k < KSZ; k++) s[k] = 0.f;
            for (int u = 0; u < 32; u++) {
                float acc = 0.f;
                #pragma unroll
                for (int t = 0; t < T_; t++) acc += p[t] * w1s[u * 16 + t];
                float g = tanhf(acc);
                #pragma unroll
                for (int k = 0; k < KSZ; k++) s[k] += g * w2s[k * 32 + u];
            }
            float m = s[0];
            #pragma unroll
            for (int k = 1; k < KSZ; k++) m = fmaxf(m, s[k]);
            float e[KSZ], sum = 0.f;
            #pragma unroll
            for (int k = 0; k < KSZ; k++) { e[k] = expf(s[k] - m); sum += e[k]; }
            float inv = 1.0f / sum;
            #pragma unroll
            for (int k = 0; k < KSZ; k++)
                d_Kern[(b * C_ + c) * KSZ + k] = e[k] * inv;
        }
        return;
    }

    const int o = blockIdx.x;
    const int lane = tid & 31;
    const int wrp  = tid >> 5;

    for (int i = tid; i < C_ * PSROW; i += 128) ps[i] = 0.f;
    __syncthreads();
    const float4* pp = reinterpret_cast<const float4*>(d_pooled + b * C_ * T_);
    for (int i = tid; i < C_ * T_ / 4; i += 128) {
        float4 v = pp[i];
        int e0 = i * 4;
        int c = e0 >> 4, t = e0 & 15;
        float* r = &ps[c * PSROW + PAD + t];
        r[0] = v.x; r[1] = v.y; r[2] = v.z; r[3] = v.w;
    }
    __syncthreads();

    float acc[T_];
    #pragma unroll
    for (int t = 0; t < T_; t++) acc[t] = 0.f;

    const float* w = Wl1 + o * (C_ * KSZ);
    #pragma unroll
    for (int ii = 0; ii < 2; ii++) {
        const int i = tid * 2 + ii;
        float wk[KSZ];
        #pragma unroll
        for (int k = 0; k < KSZ; k++) wk[k] = w[i * KSZ + k];
        float pv[T_ + 2 * PAD];
        #pragma unroll
        for (int j = 0; j < T_ + 2 * PAD; j++) pv[j] = ps[i * PSROW + j];
        #pragma unroll
        for (int t = 0; t < T_; t++) {
            #pragma unroll
            for (int k = 0; k < KSZ; k++)
                acc[t] += wk[k] * pv[t + k];
        }
    }

    #pragma unroll
    for (int off = 16; off > 0; off >>= 1) {
        #pragma unroll
        for (int t = 0; t < T_; t++)
            acc[t] += __shfl_xor_sync(0xffffffffu, acc[t], off);
    }
    if (lane == 0) {
        #pragma unroll
        for (int t = 0; t < T_; t++) red[wrp][t] = acc[t];
    }
    __syncthreads();
    if (tid < T_) {
        float s = red[0][tid] + red[1][tid] + red[2][tid] + red[3][tid];
        d_Yt[(b * T_ + tid) * 64 + o] = tanhf(s);
    }
}

// ---------------------------------------------------------------------------
// Kernel 3: main via TMA. Block per (b,c), 196 threads.
//   16 bulk loads into 19-slot smem ring; gates overlap the loads; per-lane
//   sliding-window conv in regs; out[t] -> slot (t+16)%19 (lane-private reuse
//   of freed in-slots); 16 bulk stores at the end.
// ---------------------------------------------------------------------------
__global__ void __launch_bounds__(196)
tam_main_kernel(const float* __restrict__ x, float* __restrict__ out,
                const float* __restrict__ Wl2)   // [256][64]
{
    extern __shared__ __align__(128) char smem[];
    float4* sm4 = reinterpret_cast<float4*>(smem);
    const uint32_t mbar = smem_u32(smem + NSLOT * SLICE_BYTES);
    __shared__ float lrs[T_];

    const int bc  = blockIdx.x;
    const int b   = bc >> 8;
    const int c   = bc & (C_ - 1);
    const int tid = threadIdx.x;     // 0..195

    const size_t row0 = (size_t)(b * T_ * C_ + c);   // row index of t=0 slice
    const uint32_t s_base = smem_u32(smem);

    if (tid == 0) MBAR_INIT(mbar, 1);
    __syncthreads();
    if (tid == 0) {
        MBAR_EXPECT(mbar, (uint32_t)(T_ * SLICE_BYTES));
        #pragma unroll
        for (int t = 0; t < T_; t++)
            BULK_G2S(s_base + t * SLICE_BYTES,
                     x + (row0 + (size_t)t * C_) * HW_,
                     (uint32_t)SLICE_BYTES, mbar);
    }

    // gates + kernel taps, overlapped with TMA latency
    if (tid < T_) {
        const float4* wv = reinterpret_cast<const float4*>(Wl2 + c * 64);
        const float4* yv = reinterpret_cast<const float4*>(d_Yt + (b * T_ + tid) * 64);
        float acc = 0.f;
        #pragma unroll
        for (int q = 0; q < 16; q++) {
            float4 wq = wv[q], yq = yv[q];
            acc += wq.x * yq.x + wq.y * yq.y + wq.z * yq.z + wq.w * yq.w;
        }
        lrs[tid] = 1.0f / (1.0f + expf(-acc));
    }
    float kr[KSZ];
    #pragma unroll
    for (int k = 0; k < KSZ; k++) kr[k] = d_Kern[bc * KSZ + k];
    __syncthreads();

    float lr[T_];
    #pragma unroll
    for (int t = 0; t < T_; t++) lr[t] = lrs[t];

    MBAR_WAIT(mbar, 0);

    // per-lane sliding window; slot reuse is lane-private -> no syncs needed
    float4 g[T_];
    #pragma unroll
    for (int s = 0; s < T_ + PAD; s++) {
        if (s < T_) {
            float4 v = sm4[s * HW4_ + tid];
            float l = lr[s];
            g[s].x = v.x * l; g[s].y = v.y * l; g[s].z = v.z * l; g[s].w = v.w * l;
        }
        if (s >= PAD) {
            const int t = s - PAD;
            float4 a; a.x = a.y = a.z = a.w = 0.f;
            #pragma unroll
            for (int k = 0; k < KSZ; k++) {
                int u = t + k - PAD;
                if (u >= 0 && u < T_) {          // constant-folded
                    float kk = kr[k];
                    a.x += kk * g[u].x;
                    a.y += kk * g[u].y;
                    a.z += kk * g[u].z;
                    a.w += kk * g[u].w;
                }
            }
            sm4[((t + T_) % NSLOT) * HW4_ + tid] = a;   // t>=3 reuses dead in[t-3]
        }
    }

    __syncthreads();
    if (tid == 0) {
        FENCE_ASYNC();
        #pragma unroll
        for (int t = 0; t < T_; t++)
            BULK_S2G(out + (row0 + (size_t)t * C_) * HW_,
                     s_base + ((t + T_) % NSLOT) * SLICE_BYTES,
                     (uint32_t)SLICE_BYTES);
        BULK_COMMIT();
        BULK_WAIT0();
    }
    __syncthreads();
}

// ---------------------------------------------------------------------------
extern "C" void kernel_launch(void* const* d_in, const int* in_sizes, int n_in,
                              void* d_out, int out_size) {
    const float* x   = (const float*)d_in[0];
    const float* W1  = (const float*)d_in[1];
    const float* W2  = (const float*)d_in[2];
    const float* Wl1 = (const float*)d_in[3];
    const float* Wl2 = (const float*)d_in[4];
    float* out = (float*)d_out;

    static bool attr_done = false;
    if (!attr_done) {
        cudaFuncSetAttribute(pool_kernel,
            cudaFuncAttributeMaxDynamicSharedMemorySize, POOL_SMEM);
        cudaFuncSetAttribute(tam_main_kernel,
            cudaFuncAttributeMaxDynamicSharedMemorySize, MAIN_SMEM);
        attr_done = true;
    }

    pool_kernel<<<(B_ * T_ * C_) / POOL_ROWS, 512, POOL_SMEM>>>(x);
    coeff_kernel<<<dim3(65, B_), 128>>>(Wl1, W1, W2);
    tam_main_kernel<<<NBC, 196, MAIN_SMEM>>>(x, out, Wl2);
}

// round 10
// speedup vs baseline: 1.0537x; 1.0050x over previous
#include <cuda_runtime.h>
#include <math.h>
#include <stdint.h>

#define KSZ 7
#define PAD 3

#define B_  8
#define T_  16
#define C_  256
#define HW_ 784
#define HW4_ 196                  // float4 per full slice
#define NBC (B_ * C_)             // 2048
#define PSROW (T_ + 2 * PAD + 1)  // 23

// main kernel: half-slice blocks
#define HHW4 98                   // float4 per half slice
#define HBYTES 1568               // bytes per half slice
#define MAIN_SMEM (T_ * HBYTES + 16)

#define POOL_ROWS 16
#define POOL_BYTES (POOL_ROWS * HW_ * 4)   // 50176
#define POOL_SMEM (POOL_BYTES + 16)

// Scratch (no allocations allowed)
__device__ float d_pooled[B_ * C_ * T_];      // [b][c][t]
__device__ float d_Kern[B_ * C_ * KSZ];       // [b][c][k]
__device__ float d_Yt[B_ * T_ * 64];          // [b][t][o]

// ---------------- PTX helpers ----------------
__device__ __forceinline__ uint32_t smem_u32(const void* p) {
    return (uint32_t)__cvta_generic_to_shared(p);
}
#define MBAR_INIT(a, n) \
    asm volatile("mbarrier.init.shared.b64 [%0], %1;" :: "r"(a), "r"(n) : "memory")
#define MBAR_EXPECT(a, bytes) \
    asm volatile("mbarrier.arrive.expect_tx.shared.b64 _, [%0], %1;" :: "r"(a), "r"(bytes) : "memory")
#define MBAR_WAIT(a, ph) do {                                                   \
    uint32_t _done = 0;                                                         \
    while (!_done) {                                                            \
        asm volatile("{\n\t.reg .pred p;\n\t"                                   \
            "mbarrier.try_wait.parity.acquire.cta.shared::cta.b64 p, [%1], %2, 0x989680;\n\t" \
            "selp.b32 %0, 1, 0, p;\n\t}"                                        \
            : "=r"(_done) : "r"(a), "r"(ph) : "memory");                        \
    }                                                                           \
} while (0)
#define BULK_G2S(dst_s, src_g, bytes, mbar) \
    asm volatile("cp.async.bulk.shared::cluster.global.mbarrier::complete_tx::bytes [%0], [%1], %2, [%3];" \
        :: "r"(dst_s), "l"(src_g), "r"(bytes), "r"(mbar) : "memory")
#define BULK_S2G(dst_g, src_s, bytes) \
    asm volatile("cp.async.bulk.global.shared::cta.bulk_group [%0], [%1], %2;" \
        :: "l"(dst_g), "r"(src_s), "r"(bytes) : "memory")
#define BULK_COMMIT() asm volatile("cp.async.bulk.commit_group;" ::: "memory")
#define BULK_WAIT0()  asm volatile("cp.async.bulk.wait_group 0;" ::: "memory")
#define FENCE_ASYNC() asm volatile("fence.proxy.async;" ::: "memory")

// ---------------------------------------------------------------------------
// Kernel 1: spatial mean pool via bulk-copy. Block = 16 contiguous rows
// (50 KB), 512 threads; one bulk load, warp-per-row reduce from smem.
// (identical to the R7 passing version)
// ---------------------------------------------------------------------------
__global__ void __launch_bounds__(512)
pool_kernel(const float* __restrict__ x) {
    extern __shared__ __align__(128) char smem[];
    float4* sm4 = reinterpret_cast<float4*>(smem);
    const uint32_t mbar = smem_u32(smem + POOL_BYTES);

    const int tid  = threadIdx.x;
    const int warp = tid >> 5;
    const int lane = tid & 31;
    const int row0 = blockIdx.x * POOL_ROWS;

    if (tid == 0) MBAR_INIT(mbar, 1);
    __syncthreads();
    if (tid == 0) {
        MBAR_EXPECT(mbar, (uint32_t)POOL_BYTES);
        BULK_G2S(smem_u32(smem), x + (size_t)row0 * HW_, (uint32_t)POOL_BYTES, mbar);
    }
    MBAR_WAIT(mbar, 0);

    const float4* r = sm4 + warp * HW4_;
    float s = 0.f;
    #pragma unroll 7
    for (int i = lane; i < HW4_; i += 32) {
        float4 v = r[i];
        s += (v.x + v.y) + (v.z + v.w);
    }
    #pragma unroll
    for (int o = 16; o > 0; o >>= 1) s += __shfl_xor_sync(0xffffffffu, s, o);

    if (lane == 0) {
        int row = row0 + warp;          // (b*T + t)*C + c
        int c  = row & (C_ - 1);
        int bt = row >> 8;
        int t  = bt & (T_ - 1);
        int b  = bt >> 4;
        d_pooled[(b * C_ + c) * T_ + t] = s * (1.0f / (float)HW_);
    }
}

// ---------------------------------------------------------------------------
// Kernel 2: fused coefficients (unchanged). Grid = (65, 8), 128 threads.
// ---------------------------------------------------------------------------
__global__ void coeff_kernel(const float* __restrict__ Wl1,   // [64][256][7]
                             const float* __restrict__ W1,    // [32][16]
                             const float* __restrict__ W2)    // [7][32]
{
    __shared__ float ps[C_ * PSROW];
    __shared__ float red[4][T_];
    __shared__ float w1s[32 * 16];
    __shared__ float w2s[7 * 32];

    const int b   = blockIdx.y;
    const int tid = threadIdx.x;

    if (blockIdx.x == 64) {
        for (int i = tid; i < 512; i += 128) w1s[i] = W1[i];
        for (int i = tid; i < 224; i += 128) w2s[i] = W2[i];
        __syncthreads();

        #pragma unroll
        for (int cc = 0; cc < 2; cc++) {
            const int c = tid + cc * 128;
            float p[T_];
            const float4* pp = reinterpret_cast<const float4*>(d_pooled + (b * C_ + c) * T_);
            #pragma unroll
            for (int q = 0; q < 4; q++) {
                float4 v = pp[q];
                p[q*4+0]=v.x; p[q*4+1]=v.y; p[q*4+2]=v.z; p[q*4+3]=v.w;
            }
            float s[KSZ];
            #pragma unroll
            for (int k = 0; k < KSZ; k++) s[k] = 0.f;
            for (int u = 0; u < 32; u++) {
                float acc = 0.f;
                #pragma unroll
                for (int t = 0; t < T_; t++) acc += p[t] * w1s[u * 16 + t];
                float g = tanhf(acc);
                #pragma unroll
                for (int k = 0; k < KSZ; k++) s[k] += g * w2s[k * 32 + u];
            }
            float m = s[0];
            #pragma unroll
            for (int k = 1; k < KSZ; k++) m = fmaxf(m, s[k]);
            float e[KSZ], sum = 0.f;
            #pragma unroll
            for (int k = 0; k < KSZ; k++) { e[k] = expf(s[k] - m); sum += e[k]; }
            float inv = 1.0f / sum;
            #pragma unroll
            for (int k = 0; k < KSZ; k++)
                d_Kern[(b * C_ + c) * KSZ + k] = e[k] * inv;
        }
        return;
    }

    const int o = blockIdx.x;
    const int lane = tid & 31;
    const int wrp  = tid >> 5;

    for (int i = tid; i < C_ * PSROW; i += 128) ps[i] = 0.f;
    __syncthreads();
    const float4* pp = reinterpret_cast<const float4*>(d_pooled + b * C_ * T_);
    for (int i = tid; i < C_ * T_ / 4; i += 128) {
        float4 v = pp[i];
        int e0 = i * 4;
        int c = e0 >> 4, t = e0 & 15;
        float* r = &ps[c * PSROW + PAD + t];
        r[0] = v.x; r[1] = v.y; r[2] = v.z; r[3] = v.w;
    }
    __syncthreads();

    float acc[T_];
    #pragma unroll
    for (int t = 0; t < T_; t++) acc[t] = 0.f;

    const float* w = Wl1 + o * (C_ * KSZ);
    #pragma unroll
    for (int ii = 0; ii < 2; ii++) {
        const int i = tid * 2 + ii;
        float wk[KSZ];
        #pragma unroll
        for (int k = 0; k < KSZ; k++) wk[k] = w[i * KSZ + k];
        float pv[T_ + 2 * PAD];
        #pragma unroll
        for (int j = 0; j < T_ + 2 * PAD; j++) pv[j] = ps[i * PSROW + j];
        #pragma unroll
        for (int t = 0; t < T_; t++) {
            #pragma unroll
            for (int k = 0; k < KSZ; k++)
                acc[t] += wk[k] * pv[t + k];
        }
    }

    #pragma unroll
    for (int off = 16; off > 0; off >>= 1) {
        #pragma unroll
        for (int t = 0; t < T_; t++)
            acc[t] += __shfl_xor_sync(0xffffffffu, acc[t], off);
    }
    if (lane == 0) {
        #pragma unroll
        for (int t = 0; t < T_; t++) red[wrp][t] = acc[t];
    }
    __syncthreads();
    if (tid < T_) {
        float s = red[0][tid] + red[1][tid] + red[2][tid] + red[3][tid];
        d_Yt[(b * T_ + tid) * 64 + o] = tanhf(s);
    }
}

// ---------------------------------------------------------------------------
// Kernel 3: main via bulk-copy, half-slice blocks for 8 CTAs/SM.
// 4096 blocks = (b,c,half); 98 threads; 16 bulk loads (1568 B each) into
// smem; window lives in registers so out[t] overwrites slot t; bulk stores;
// trailing __syncthreads (matches R7-passing exit sequence).
// ---------------------------------------------------------------------------
__global__ void __launch_bounds__(98)
tam_main_kernel(const float* __restrict__ x, float* __restrict__ out,
                const float* __restrict__ Wl2)   // [256][64]
{
    extern __shared__ __align__(128) char smem[];
    float4* sm4 = reinterpret_cast<float4*>(smem);
    const uint32_t mbar = smem_u32(smem + T_ * HBYTES);
    __shared__ float lrs[T_];

    const int id   = blockIdx.x;        // 0..4095
    const int bc   = id >> 1;
    const int half = id & 1;
    const int b    = bc >> 8;
    const int c    = bc & (C_ - 1);
    const int tid  = threadIdx.x;       // 0..97

    const size_t row0  = (size_t)(b * T_ * C_ + c);
    const size_t goff  = row0 * HW_ + half * (HHW4 * 4);   // float offset
    const uint32_t s_base = smem_u32(smem);

    if (tid == 0) MBAR_INIT(mbar, 1);
    __syncthreads();
    if (tid == 0) {
        MBAR_EXPECT(mbar, (uint32_t)(T_ * HBYTES));
        #pragma unroll
        for (int t = 0; t < T_; t++)
            BULK_G2S(s_base + t * HBYTES,
                     x + goff + (size_t)t * (C_ * HW_),
                     (uint32_t)HBYTES, mbar);
    }

    // gates + taps, overlapped with bulk-load latency
    if (tid < T_) {
        const float4* wv = reinterpret_cast<const float4*>(Wl2 + c * 64);
        const float4* yv = reinterpret_cast<const float4*>(d_Yt + (b * T_ + tid) * 64);
        float acc = 0.f;
        #pragma unroll
        for (int q = 0; q < 16; q++) {
            float4 wq = wv[q], yq = yv[q];
            acc += wq.x * yq.x + wq.y * yq.y + wq.z * yq.z + wq.w * yq.w;
        }
        lrs[tid] = 1.0f / (1.0f + expf(-acc));
    }
    float kr[KSZ];
    #pragma unroll
    for (int k = 0; k < KSZ; k++) kr[k] = d_Kern[bc * KSZ + k];
    __syncthreads();

    float lr[T_];
    #pragma unroll
    for (int t = 0; t < T_; t++) lr[t] = lrs[t];

    MBAR_WAIT(mbar, 0);

    // whole window in registers; outputs overwrite their own slot
    float4 g[T_];
    #pragma unroll
    for (int t = 0; t < T_; t++) {
        float4 v = sm4[t * HHW4 + tid];
        float l = lr[t];
        g[t].x = v.x * l; g[t].y = v.y * l; g[t].z = v.z * l; g[t].w = v.w * l;
    }
    #pragma unroll
    for (int t = 0; t < T_; t++) {
        float4 a; a.x = a.y = a.z = a.w = 0.f;
        #pragma unroll
        for (int k = 0; k < KSZ; k++) {
            int u = t + k - PAD;
            if (u >= 0 && u < T_) {          // constant-folded
                float kk = kr[k];
                a.x += kk * g[u].x;
                a.y += kk * g[u].y;
                a.z += kk * g[u].z;
                a.w += kk * g[u].w;
            }
        }
        sm4[t * HHW4 + tid] = a;
    }

    __syncthreads();
    if (tid == 0) {
        FENCE_ASYNC();
        #pragma unroll
        for (int t = 0; t < T_; t++)
            BULK_S2G(out + goff + (size_t)t * (C_ * HW_),
                     s_base + t * HBYTES, (uint32_t)HBYTES);
        BULK_COMMIT();
        BULK_WAIT0();
    }
    __syncthreads();
}

// ---------------------------------------------------------------------------
extern "C" void kernel_launch(void* const* d_in, const int* in_sizes, int n_in,
                              void* d_out, int out_size) {
    const float* x   = (const float*)d_in[0];
    const float* W1  = (const float*)d_in[1];
    const float* W2  = (const float*)d_in[2];
    const float* Wl1 = (const float*)d_in[3];
    const float* Wl2 = (const float*)d_in[4];
    float* out = (float*)d_out;

    static bool attr_done = false;
    if (!attr_done) {
        cudaFuncSetAttribute(pool_kernel,
            cudaFuncAttributeMaxDynamicSharedMemorySize, POOL_SMEM);
        cudaFuncSetAttribute(tam_main_kernel,
            cudaFuncAttributeMaxDynamicSharedMemorySize, MAIN_SMEM);
        attr_done = true;
    }

    pool_kernel<<<(B_ * T_ * C_) / POOL_ROWS, 512, POOL_SMEM>>>(x);
    coeff_kernel<<<dim3(65, B_), 128>>>(Wl1, W1, W2);
    tam_main_kernel<<<NBC * 2, 98, MAIN_SMEM>>>(x, out, Wl2);
}